// round 9
// baseline (speedup 1.0000x reference)
#include <cuda_runtime.h>
#include <cuda_fp16.h>

#define N_NODES  50000
#define N_EDGES  800000
#define N_GRAPHS 256
#define DF       128
#define NHID     256
#define NOUT     768
#define SCAN_B   ((N_NODES + 1023) / 1024)

// ---------------- scratch (device globals: no allocs allowed) ----------------
__device__ uint4 g_h16[N_NODES * DF / 8]; // layer features, fp16 (GEMM input / pool)
__device__ uint4 g_y16[N_NODES * DF / 8]; // dinv-scaled GEMM out, fp16 (gather src)
__device__ int   g_deg[N_NODES];
__device__ int   g_rowptr[N_NODES + 1];
__device__ int   g_cur[N_NODES];
__device__ int   g_eidx[N_EDGES];         // CSR-by-dst: src node ids
__device__ float g_dinv[N_NODES];
__device__ float g_pool[N_GRAPHS * DF];
__device__ float g_mlp[N_GRAPHS * NHID];
__device__ int   g_part[64];
__device__ int   g_part2[64];
__device__ int   g_is64;                  // 1 if indices are int64, 0 if int32

__device__ __forceinline__ int idx_at(const void* p, long long i, int is64) {
    if (is64) return (int)((const long long*)p)[i];
    return ((const int*)p)[i];
}

// ---------------- dtype detection ----------------
__global__ void k_detect(const void* ei) {
    if (threadIdx.x == 0) g_is64 = 1;
    __syncthreads();
    long long v = ((const long long*)ei)[threadIdx.x];  // 512 threads
    if (v < 0 || v >= N_NODES) atomicAnd(&g_is64, 0);
}

// ---------------- graph preprocessing ----------------
__global__ void k_zero() {
    int i = blockIdx.x * blockDim.x + threadIdx.x;
    if (i < N_NODES) g_deg[i] = 0;
}

__global__ void k_deg(const void* __restrict__ ei) {
    int e = blockIdx.x * blockDim.x + threadIdx.x;
    if (e < N_EDGES) {
        int d = idx_at(ei, (long long)N_EDGES + e, g_is64);   // dst row
        atomicAdd(&g_deg[d], 1);
    }
}

__global__ void k_scan1() {
    __shared__ int s[1024];
    int tid = threadIdx.x;
    int i = blockIdx.x * 1024 + tid;
    s[tid] = (i < N_NODES) ? g_deg[i] : 0;
    __syncthreads();
    #pragma unroll
    for (int off = 1; off < 1024; off <<= 1) {
        int t = (tid >= off) ? s[tid - off] : 0;
        __syncthreads();
        s[tid] += t;
        __syncthreads();
    }
    if (i < N_NODES) g_rowptr[i + 1] = s[tid];
    if (tid == 1023) g_part[blockIdx.x] = s[1023];
}

__global__ void k_scan2() {
    if (threadIdx.x == 0) {
        int a = 0;
        for (int b = 0; b < SCAN_B; b++) { g_part2[b] = a; a += g_part[b]; }
    }
}

// scan3 + prep fused: finalize rowptr, derive cur & dinv
__global__ void k_scan3() {
    int i = blockIdx.x * blockDim.x + threadIdx.x;
    if (i == 0) g_rowptr[0] = 0;
    if (i < N_NODES) {
        int d  = g_deg[i];
        int rp = g_rowptr[i + 1] + g_part2[i >> 10];
        g_rowptr[i + 1] = rp;
        g_cur[i]  = rp - d;
        g_dinv[i] = rsqrtf((float)(d + 1));   // +1 self loop; always > 0
    }
}

__global__ void k_fill(const void* __restrict__ ei) {
    int e = blockIdx.x * blockDim.x + threadIdx.x;
    if (e < N_EDGES) {
        int is64 = g_is64;
        int s = idx_at(ei, e, is64);                         // src
        int d = idx_at(ei, (long long)N_EDGES + e, is64);    // dst
        int pos = atomicAdd(&g_cur[d], 1);
        g_eidx[pos] = s;
    }
}

// ---------------- tensor-core GEMM (tf32 mma.sync) ----------------
// y16[v,:] = fp16( (X @ W)[v,:] * dinv[v] ).
// X: fp32 (layer 1) or fp16 g_h16 (layers 2/3). W:[128,128] fp32.
// Block tile 128(M) x 128(N), K chunked by 32. 8 warps 4x2, warp tile 32x64.
#define BK   32
#define PADA 36
#define PADB 136

__device__ __forceinline__ unsigned f2tf(float x) {
    unsigned u;
    asm("cvt.rna.tf32.f32 %0, %1;" : "=r"(u) : "f"(x));
    return u;
}

__device__ __forceinline__ void mma_tf32(float* d,
                                         const unsigned* a, const unsigned* b,
                                         const float* c) {
    asm volatile(
        "mma.sync.aligned.m16n8k8.row.col.f32.tf32.tf32.f32 "
        "{%0,%1,%2,%3}, {%4,%5,%6,%7}, {%8,%9}, {%10,%11,%12,%13};\n"
        : "=f"(d[0]), "=f"(d[1]), "=f"(d[2]), "=f"(d[3])
        : "r"(a[0]), "r"(a[1]), "r"(a[2]), "r"(a[3]),
          "r"(b[0]), "r"(b[1]),
          "f"(c[0]), "f"(c[1]), "f"(c[2]), "f"(c[3]));
}

__global__ void __launch_bounds__(256) k_gemm_tc(const float* __restrict__ Xf,
                                                 int use_h16,
                                                 const float* __restrict__ W) {
    __shared__ unsigned As[128 * PADA];
    __shared__ unsigned Bs[BK * PADB];
    int tid  = threadIdx.x;
    int wid  = tid >> 5, lane = tid & 31;
    int wm   = wid >> 1, wn = wid & 1;       // 4 x 2 warps
    int grp  = lane >> 2, tig = lane & 3;
    int row0 = blockIdx.x * 128;

    float acc[2][8][4] = {};

    for (int kt = 0; kt < 128; kt += BK) {
        #pragma unroll
        for (int i = 0; i < 4; i++) {        // A tile 128x32
            int linear = (tid + i * 256) * 4;
            int r = linear >> 5, c = linear & 31;
            int grow = row0 + r;
            uint4 u;
            if (use_h16) {
                uint2 hv = (grow < N_NODES)
                    ? ((const uint2*)g_h16)[grow * 32 + ((kt + c) >> 2)]
                    : make_uint2(0, 0);
                float2 f0 = __half22float2(*(__half2*)&hv.x);
                float2 f1 = __half22float2(*(__half2*)&hv.y);
                u = make_uint4(f2tf(f0.x), f2tf(f0.y), f2tf(f1.x), f2tf(f1.y));
            } else {
                float4 v = (grow < N_NODES)
                    ? *(const float4*)&Xf[grow * 128 + kt + c]
                    : make_float4(0.f, 0.f, 0.f, 0.f);
                u = make_uint4(f2tf(v.x), f2tf(v.y), f2tf(v.z), f2tf(v.w));
            }
            *(uint4*)&As[r * PADA + c] = u;
        }
        #pragma unroll
        for (int i = 0; i < 4; i++) {        // B tile 32x128
            int linear = (tid + i * 256) * 4;
            int k = linear >> 7, n = linear & 127;
            float4 v = *(const float4*)&W[(kt + k) * 128 + n];
            uint4 u = make_uint4(f2tf(v.x), f2tf(v.y), f2tf(v.z), f2tf(v.w));
            *(uint4*)&Bs[k * PADB + n] = u;
        }
        __syncthreads();

        #pragma unroll
        for (int ka = 0; ka < 4; ka++) {
            int kb = ka * 8;
            unsigned a[2][4], b[8][2];
            #pragma unroll
            for (int m = 0; m < 2; m++) {
                int r = wm * 32 + m * 16 + grp;
                a[m][0] = As[r * PADA + kb + tig];
                a[m][1] = As[(r + 8) * PADA + kb + tig];
                a[m][2] = As[r * PADA + kb + tig + 4];
                a[m][3] = As[(r + 8) * PADA + kb + tig + 4];
            }
            #pragma unroll
            for (int n = 0; n < 8; n++) {
                int cn = wn * 64 + n * 8 + grp;
                b[n][0] = Bs[(kb + tig) * PADB + cn];
                b[n][1] = Bs[(kb + tig + 4) * PADB + cn];
            }
            #pragma unroll
            for (int m = 0; m < 2; m++)
                #pragma unroll
                for (int n = 0; n < 8; n++)
                    mma_tf32(acc[m][n], a[m], b[n], acc[m][n]);
        }
        __syncthreads();
    }

    // epilogue: scale by dinv, convert to fp16, half2 stores
    __half2* yp = (__half2*)g_y16;
    #pragma unroll
    for (int m = 0; m < 2; m++) {
        #pragma unroll
        for (int half = 0; half < 2; half++) {
            int row = row0 + wm * 32 + m * 16 + grp + half * 8;
            if (row < N_NODES) {
                float dv = g_dinv[row];
                #pragma unroll
                for (int n = 0; n < 8; n++) {
                    int col = wn * 64 + n * 8 + 2 * tig;
                    yp[row * 64 + (col >> 1)] =
                        __floats2half2_rn(acc[m][n][half * 2] * dv,
                                          acc[m][n][half * 2 + 1] * dv);
                }
            }
        }
    }
}

// ---------------- gather-sum: warp/node, 2 edges in parallel per warp --------
// h16[v,:] = fp16( act( dinv[v] * (y'[v,:] + sum_{s->v} y'[s,:]) + b ) )
// 16 lanes x uint4 (8 fp16) = 256B row. Warp halves take even/odd edges.
__device__ __forceinline__ void acc8(float2* a, uint4 r) {
    float2 p0 = __half22float2(*(__half2*)&r.x);
    float2 p1 = __half22float2(*(__half2*)&r.y);
    float2 p2 = __half22float2(*(__half2*)&r.z);
    float2 p3 = __half22float2(*(__half2*)&r.w);
    a[0].x += p0.x; a[0].y += p0.y;
    a[1].x += p1.x; a[1].y += p1.y;
    a[2].x += p2.x; a[2].y += p2.y;
    a[3].x += p3.x; a[3].y += p3.y;
}

__global__ void k_gather(const float* __restrict__ b, int relu) {
    int t = blockIdx.x * blockDim.x + threadIdx.x;
    int v = t >> 5;
    int lane = t & 31;
    if (v >= N_NODES) return;
    int half = lane >> 4;       // 0 or 1: which edge parity this half handles
    int sub  = lane & 15;       // 16 lanes cover the 256B row

    const uint4* yp = (const uint4*)g_y16;
    float2 acc[4] = {{0.f,0.f},{0.f,0.f},{0.f,0.f},{0.f,0.f}};
    if (half == 0) acc8(acc, yp[v * 16 + sub]);          // self loop

    int beg = g_rowptr[v], end = g_rowptr[v + 1];
    int e = beg + half;
    for (; e + 2 < end; e += 4) {                        // 2 rows in flight/half
        int s0 = g_eidx[e];
        int s1 = g_eidx[e + 2];
        uint4 r0 = yp[s0 * 16 + sub];
        uint4 r1 = yp[s1 * 16 + sub];
        acc8(acc, r0);
        acc8(acc, r1);
    }
    for (; e < end; e += 2) acc8(acc, yp[g_eidx[e] * 16 + sub]);

    // combine the two halves (lane i += lane i+16)
    #pragma unroll
    for (int i = 0; i < 4; i++) {
        acc[i].x += __shfl_down_sync(0xffffffffu, acc[i].x, 16);
        acc[i].y += __shfl_down_sync(0xffffffffu, acc[i].y, 16);
    }

    if (half == 0) {
        float dv = g_dinv[v];
        const float4* bp = (const float4*)b;
        float4 b0 = bp[sub * 2], b1 = bp[sub * 2 + 1];
        float o0 = dv * acc[0].x + b0.x, o1 = dv * acc[0].y + b0.y;
        float o2 = dv * acc[1].x + b0.z, o3 = dv * acc[1].y + b0.w;
        float o4 = dv * acc[2].x + b1.x, o5 = dv * acc[2].y + b1.y;
        float o6 = dv * acc[3].x + b1.z, o7 = dv * acc[3].y + b1.w;
        if (relu) {
            o0 = fmaxf(o0, 0.f); o1 = fmaxf(o1, 0.f);
            o2 = fmaxf(o2, 0.f); o3 = fmaxf(o3, 0.f);
            o4 = fmaxf(o4, 0.f); o5 = fmaxf(o5, 0.f);
            o6 = fmaxf(o6, 0.f); o7 = fmaxf(o7, 0.f);
        }
        uint4 w;
        *(__half2*)&w.x = __floats2half2_rn(o0, o1);
        *(__half2*)&w.y = __floats2half2_rn(o2, o3);
        *(__half2*)&w.z = __floats2half2_rn(o4, o5);
        *(__half2*)&w.w = __floats2half2_rn(o6, o7);
        g_h16[v * 16 + sub] = w;
    }
}

// ---------------- global mean pool: one block per graph, batch is sorted -----
__global__ void k_poolg(const void* __restrict__ batch) {
    int g = blockIdx.x;
    int j = threadIdx.x;     // 128 threads = feature dims
    int is64 = g_is64;
    int lo = 0, hi = N_NODES;
    while (lo < hi) { int m = (lo + hi) >> 1; if (idx_at(batch, m, is64) < g) lo = m + 1; else hi = m; }
    int beg = lo;
    lo = 0; hi = N_NODES;
    while (lo < hi) { int m = (lo + hi) >> 1; if (idx_at(batch, m, is64) <= g) lo = m + 1; else hi = m; }
    int end = lo;
    const __half* hp = (const __half*)g_h16;
    float acc = 0.f;
    for (int v = beg; v < end; v++) acc += __half2float(hp[v * DF + j]);
    float inv = (end > beg) ? 1.f / (float)(end - beg) : 0.f;
    g_pool[g * DF + j] = acc * inv;
}

// ---------------- MLP head (4 graphs per block for weight reuse) -------------
__global__ void k_mlp1(const float* __restrict__ Wm1, const float* __restrict__ bm1) {
    __shared__ float p[4][DF];
    int g0 = blockIdx.x * 4;
    int j = threadIdx.x;                 // 256 threads
    #pragma unroll
    for (int i = j; i < 4 * DF; i += NHID) p[i >> 7][i & 127] = g_pool[g0 * DF + i];
    __syncthreads();
    float bias = bm1[j];
    float a0 = bias, a1 = bias, a2 = bias, a3 = bias;
    #pragma unroll 4
    for (int k = 0; k < DF; k++) {
        float w = Wm1[k * NHID + j];
        a0 += p[0][k] * w; a1 += p[1][k] * w;
        a2 += p[2][k] * w; a3 += p[3][k] * w;
    }
    g_mlp[(g0 + 0) * NHID + j] = fmaxf(a0, 0.f);
    g_mlp[(g0 + 1) * NHID + j] = fmaxf(a1, 0.f);
    g_mlp[(g0 + 2) * NHID + j] = fmaxf(a2, 0.f);
    g_mlp[(g0 + 3) * NHID + j] = fmaxf(a3, 0.f);
}

__global__ void k_mlp2(const float* __restrict__ Wm2, const float* __restrict__ bm2,
                       float* __restrict__ out) {
    __shared__ float p[4][NHID];
    int g0 = blockIdx.x * 4;
    int j = threadIdx.x;                 // 768 threads
    for (int i = j; i < 4 * NHID; i += NOUT) p[i >> 8][i & 255] = g_mlp[g0 * NHID + i];
    __syncthreads();
    float bias = bm2[j];
    float a0 = bias, a1 = bias, a2 = bias, a3 = bias;
    #pragma unroll 4
    for (int k = 0; k < NHID; k++) {
        float w = Wm2[k * NOUT + j];
        a0 += p[0][k] * w; a1 += p[1][k] * w;
        a2 += p[2][k] * w; a3 += p[3][k] * w;
    }
    out[(g0 + 0) * NOUT + j] = a0;
    out[(g0 + 1) * NOUT + j] = a1;
    out[(g0 + 2) * NOUT + j] = a2;
    out[(g0 + 3) * NOUT + j] = a3;
}

// ---------------- launch ----------------
extern "C" void kernel_launch(void* const* d_in, const int* in_sizes, int n_in,
                              void* d_out, int out_size) {
    const float* x     = (const float*)d_in[0];
    const void*  ei    = d_in[1];        // int32 or int64, detected on device
    const void*  batch = d_in[2];
    const float* W1  = (const float*)d_in[3];
    const float* b1  = (const float*)d_in[4];
    const float* W2  = (const float*)d_in[5];
    const float* b2  = (const float*)d_in[6];
    const float* W3  = (const float*)d_in[7];
    const float* b3  = (const float*)d_in[8];
    const float* Wm1 = (const float*)d_in[9];
    const float* bm1 = (const float*)d_in[10];
    const float* Wm2 = (const float*)d_in[11];
    const float* bm2 = (const float*)d_in[12];
    float* out = (float*)d_out;

    const int ZB = (N_NODES + 255) / 256;
    const int EB = (N_EDGES + 255) / 256;
    const int GB = (N_NODES + 127) / 128;        // gemm row tiles
    const int WB = (N_NODES * 32 + 255) / 256;   // warp-per-node kernels

    // dtype detect + CSR build + norms
    k_detect<<<1, 512>>>(ei);
    k_zero <<<ZB, 256>>>();
    k_deg  <<<EB, 256>>>(ei);
    k_scan1<<<SCAN_B, 1024>>>();
    k_scan2<<<1, 32>>>();
    k_scan3<<<ZB, 256>>>();              // rowptr finalize + cur + dinv
    k_fill <<<EB, 256>>>(ei);

    // layer 1
    k_gemm_tc<<<GB, 256>>>(x, 0, W1);
    k_gather <<<WB, 256>>>(b1, 1);
    // layer 2
    k_gemm_tc<<<GB, 256>>>(nullptr, 1, W2);
    k_gather <<<WB, 256>>>(b2, 1);
    // layer 3 (no relu)
    k_gemm_tc<<<GB, 256>>>(nullptr, 1, W3);
    k_gather <<<WB, 256>>>(b3, 0);

    // pooling + MLP head
    k_poolg<<<N_GRAPHS, DF>>>(batch);
    k_mlp1 <<<N_GRAPHS / 4, NHID>>>(Wm1, bm1);
    k_mlp2 <<<N_GRAPHS / 4, NOUT>>>(Wm2, bm2, out);
}

// round 10
// speedup vs baseline: 1.0712x; 1.0712x over previous
#include <cuda_runtime.h>
#include <cuda_fp16.h>

#define N_NODES  50000
#define N_EDGES  800000
#define N_GRAPHS 256
#define DF       128
#define NHID     256
#define NOUT     768
#define SCAN_B   ((N_NODES + 1023) / 1024)

// ---------------- scratch (device globals: no allocs allowed) ----------------
__device__ uint4 g_h16[N_NODES * DF / 8]; // layer features, fp16
__device__ uint2 g_y16[N_NODES * DF / 4]; // dinv-scaled GEMM out, fp16 (gather src)
__device__ int   g_deg[N_NODES];
__device__ int   g_rowptr[N_NODES + 1];
__device__ int   g_cur[N_NODES];
__device__ int   g_eidx[N_EDGES];         // CSR-by-dst: src node ids
__device__ float g_dinv[N_NODES];
__device__ float g_pool[N_GRAPHS * DF];
__device__ float g_mlp[N_GRAPHS * NHID];
__device__ int   g_part[64];
__device__ int   g_is64;                  // 1 if indices are int64, 0 if int32

__device__ __forceinline__ int idx_at(const void* p, long long i, int is64) {
    if (is64) return (int)((const long long*)p)[i];
    return ((const int*)p)[i];
}

// ---------------- dtype detection ----------------
__global__ void k_detect(const void* ei) {
    if (threadIdx.x == 0) g_is64 = 1;
    __syncthreads();
    long long v = ((const long long*)ei)[threadIdx.x];  // 512 threads
    if (v < 0 || v >= N_NODES) atomicAnd(&g_is64, 0);
}

// ---------------- graph preprocessing ----------------
__global__ void k_zero() {
    int i = blockIdx.x * blockDim.x + threadIdx.x;
    if (i < N_NODES) g_deg[i] = 0;
}

__global__ void k_deg(const void* __restrict__ ei) {
    int e = blockIdx.x * blockDim.x + threadIdx.x;
    if (e < N_EDGES) {
        int d = idx_at(ei, (long long)N_EDGES + e, g_is64);   // dst row
        atomicAdd(&g_deg[d], 1);
    }
}

__global__ void k_scan1() {
    __shared__ int s[1024];
    int tid = threadIdx.x;
    int i = blockIdx.x * 1024 + tid;
    s[tid] = (i < N_NODES) ? g_deg[i] : 0;
    __syncthreads();
    #pragma unroll
    for (int off = 1; off < 1024; off <<= 1) {
        int t = (tid >= off) ? s[tid - off] : 0;
        __syncthreads();
        s[tid] += t;
        __syncthreads();
    }
    if (i < N_NODES) g_rowptr[i + 1] = s[tid];
    if (tid == 1023) g_part[blockIdx.x] = s[1023];
}

// fused: partial-prefix + rowptr finalize + cur + dinv
// each block's 256 nodes lie in exactly one 1024-chunk, so thread 0 serially
// prefixes the <=49 block partials (trivial).
__global__ void k_scan23() {
    __shared__ int base;
    int i = blockIdx.x * 256 + threadIdx.x;
    if (threadIdx.x == 0) {
        int c = (blockIdx.x * 256) >> 10;
        int a = 0;
        for (int b = 0; b < c; b++) a += g_part[b];
        base = a;
    }
    __syncthreads();
    if (i == 0) g_rowptr[0] = 0;
    if (i < N_NODES) {
        int d  = g_deg[i];
        int rp = g_rowptr[i + 1] + base;
        g_rowptr[i + 1] = rp;
        g_cur[i]  = rp - d;
        g_dinv[i] = rsqrtf((float)(d + 1));   // +1 self loop; always > 0
    }
}

__global__ void k_fill(const void* __restrict__ ei) {
    int e = blockIdx.x * blockDim.x + threadIdx.x;
    if (e < N_EDGES) {
        int is64 = g_is64;
        int s = idx_at(ei, e, is64);                         // src
        int d = idx_at(ei, (long long)N_EDGES + e, is64);    // dst
        int pos = atomicAdd(&g_cur[d], 1);
        g_eidx[pos] = s;
    }
}

// ---------------- tensor-core GEMM (fp16 m16n8k16 mma.sync, fp32 accum) ------
// y16[v,:] = fp16( (X @ W)[v,:] * dinv[v] ).
// Block tile 128(M) x 128(N), K tiled by 64. 8 warps 4x2, warp tile 32x64.
// A: row-major fp16 smem As[r][k]; B: W transposed to col-major fp16 Bs[n][k].
#define PA 72   // halves pitch (36 words: conflict-free fragment loads)
#define PB 72

__device__ __forceinline__ void mma_f16(float* d,
                                        const unsigned* a, const unsigned* b,
                                        const float* c) {
    asm volatile(
        "mma.sync.aligned.m16n8k16.row.col.f32.f16.f16.f32 "
        "{%0,%1,%2,%3}, {%4,%5,%6,%7}, {%8,%9}, {%10,%11,%12,%13};\n"
        : "=f"(d[0]), "=f"(d[1]), "=f"(d[2]), "=f"(d[3])
        : "r"(a[0]), "r"(a[1]), "r"(a[2]), "r"(a[3]),
          "r"(b[0]), "r"(b[1]),
          "f"(c[0]), "f"(c[1]), "f"(c[2]), "f"(c[3]));
}

__global__ void __launch_bounds__(256) k_gemm_h(const float* __restrict__ Xf,
                                                int use_h16,
                                                const float* __restrict__ W) {
    __shared__ __half As[128 * PA];
    __shared__ __half Bs[128 * PB];
    int tid  = threadIdx.x;
    int wid  = tid >> 5, lane = tid & 31;
    int wm   = wid >> 1, wn = wid & 1;       // 4 x 2 warps
    int grp  = lane >> 2, tig = lane & 3;
    int row0 = blockIdx.x * 128;

    float acc[2][8][4] = {};

    for (int kt = 0; kt < 128; kt += 64) {
        // ---- A tile: 128 rows x 64 halves ----
        if (use_h16) {
            #pragma unroll
            for (int i = 0; i < 4; i++) {
                int idx = tid + i * 256;          // 1024 uint4
                int r = idx >> 3, q = idx & 7;
                int grow = row0 + r;
                uint4 u = (grow < N_NODES) ? g_h16[grow * 16 + (kt >> 3) + q]
                                           : make_uint4(0, 0, 0, 0);
                *(uint4*)&As[r * PA + q * 8] = u;
            }
        } else {
            #pragma unroll
            for (int i = 0; i < 4; i++) {
                int idx = tid + i * 256;
                int r = idx >> 3, q = idx & 7;
                int grow = row0 + r;
                uint4 u = make_uint4(0, 0, 0, 0);
                if (grow < N_NODES) {
                    const float4* xp = (const float4*)&Xf[grow * 128 + kt + q * 8];
                    float4 f0 = xp[0], f1 = xp[1];
                    *(__half2*)&u.x = __floats2half2_rn(f0.x, f0.y);
                    *(__half2*)&u.y = __floats2half2_rn(f0.z, f0.w);
                    *(__half2*)&u.z = __floats2half2_rn(f1.x, f1.y);
                    *(__half2*)&u.w = __floats2half2_rn(f1.z, f1.w);
                }
                *(uint4*)&As[r * PA + q * 8] = u;
            }
        }
        // ---- B tile: W[kt..kt+63][0..127] fp32 -> Bs[n][kk] fp16 (transposed)
        #pragma unroll
        for (int i = 0; i < 16; i++) {
            int idx = tid + i * 256;              // 4096 half2 words
            int n = idx & 127, w = idx >> 7;      // w: 0..31 (k pairs)
            int k0 = kt + 2 * w;
            __half2 hv = __floats2half2_rn(W[k0 * 128 + n], W[(k0 + 1) * 128 + n]);
            *(__half2*)&Bs[n * PB + 2 * w] = hv;
        }
        __syncthreads();

        #pragma unroll
        for (int ka = 0; ka < 4; ka++) {
            int kb = ka * 16;
            unsigned a[2][4], bf[8][2];
            #pragma unroll
            for (int m = 0; m < 2; m++) {
                int r = wm * 32 + m * 16 + grp;
                a[m][0] = *(unsigned*)&As[r * PA + kb + 2 * tig];
                a[m][1] = *(unsigned*)&As[(r + 8) * PA + kb + 2 * tig];
                a[m][2] = *(unsigned*)&As[r * PA + kb + 8 + 2 * tig];
                a[m][3] = *(unsigned*)&As[(r + 8) * PA + kb + 8 + 2 * tig];
            }
            #pragma unroll
            for (int n = 0; n < 8; n++) {
                int cn = wn * 64 + n * 8 + grp;
                bf[n][0] = *(unsigned*)&Bs[cn * PB + kb + 2 * tig];
                bf[n][1] = *(unsigned*)&Bs[cn * PB + kb + 8 + 2 * tig];
            }
            #pragma unroll
            for (int m = 0; m < 2; m++)
                #pragma unroll
                for (int n = 0; n < 8; n++)
                    mma_f16(acc[m][n], a[m], bf[n], acc[m][n]);
        }
        __syncthreads();
    }

    // epilogue: scale by dinv, fp16 half2 stores
    __half2* yp = (__half2*)g_y16;
    #pragma unroll
    for (int m = 0; m < 2; m++) {
        #pragma unroll
        for (int hf = 0; hf < 2; hf++) {
            int row = row0 + wm * 32 + m * 16 + grp + hf * 8;
            if (row < N_NODES) {
                float dv = g_dinv[row];
                #pragma unroll
                for (int n = 0; n < 8; n++) {
                    int col = wn * 64 + n * 8 + 2 * tig;
                    yp[row * 64 + (col >> 1)] =
                        __floats2half2_rn(acc[m][n][hf * 2] * dv,
                                          acc[m][n][hf * 2 + 1] * dv);
                }
            }
        }
    }
}

// ---------------- gather-sum: warp/node, 32 lanes x uint2, 4-deep unroll -----
// h16[v,:] = fp16( act( dinv[v] * (y'[v,:] + sum_{s->v} y'[s,:]) + b ) )
__device__ __forceinline__ void acc_row(float4& a, uint2 raw) {
    float2 lo = __half22float2(*(__half2*)&raw.x);
    float2 hi = __half22float2(*(__half2*)&raw.y);
    a.x += lo.x; a.y += lo.y; a.z += hi.x; a.w += hi.y;
}

__global__ void k_gather(const float* __restrict__ b, int relu) {
    int t = blockIdx.x * blockDim.x + threadIdx.x;
    int v = t >> 5;
    int lane = t & 31;
    if (v >= N_NODES) return;
    const uint2* yp = (const uint2*)g_y16;
    float4 acc = make_float4(0.f, 0.f, 0.f, 0.f);
    acc_row(acc, yp[v * 32 + lane]);                // self loop
    int e = g_rowptr[v], end = g_rowptr[v + 1];
    for (; e + 3 < end; e += 4) {                   // 4 rows in flight
        int s0 = g_eidx[e],     s1 = g_eidx[e + 1];
        int s2 = g_eidx[e + 2], s3 = g_eidx[e + 3];
        uint2 r0 = yp[s0 * 32 + lane];
        uint2 r1 = yp[s1 * 32 + lane];
        uint2 r2 = yp[s2 * 32 + lane];
        uint2 r3 = yp[s3 * 32 + lane];
        acc_row(acc, r0); acc_row(acc, r1);
        acc_row(acc, r2); acc_row(acc, r3);
    }
    for (; e < end; e++) acc_row(acc, yp[g_eidx[e] * 32 + lane]);

    float dv = g_dinv[v];
    float4 bb = ((const float4*)b)[lane];
    float o0 = dv * acc.x + bb.x, o1 = dv * acc.y + bb.y;
    float o2 = dv * acc.z + bb.z, o3 = dv * acc.w + bb.w;
    if (relu) {
        o0 = fmaxf(o0, 0.f); o1 = fmaxf(o1, 0.f);
        o2 = fmaxf(o2, 0.f); o3 = fmaxf(o3, 0.f);
    }
    uint2 w;
    *(__half2*)&w.x = __floats2half2_rn(o0, o1);
    *(__half2*)&w.y = __floats2half2_rn(o2, o3);
    ((uint2*)g_h16)[v * 32 + lane] = w;
}

// ---------------- global mean pool: one block per graph, batch is sorted -----
__global__ void k_poolg(const void* __restrict__ batch) {
    int g = blockIdx.x;
    int j = threadIdx.x;     // 128 threads = feature dims
    int is64 = g_is64;
    int lo = 0, hi = N_NODES;
    while (lo < hi) { int m = (lo + hi) >> 1; if (idx_at(batch, m, is64) < g) lo = m + 1; else hi = m; }
    int beg = lo;
    lo = 0; hi = N_NODES;
    while (lo < hi) { int m = (lo + hi) >> 1; if (idx_at(batch, m, is64) <= g) lo = m + 1; else hi = m; }
    int end = lo;
    const __half* hp = (const __half*)g_h16;
    float acc = 0.f;
    for (int v = beg; v < end; v++) acc += __half2float(hp[v * DF + j]);
    float inv = (end > beg) ? 1.f / (float)(end - beg) : 0.f;
    g_pool[g * DF + j] = acc * inv;
}

// ---------------- MLP head (4 graphs per block for weight reuse) -------------
__global__ void k_mlp1(const float* __restrict__ Wm1, const float* __restrict__ bm1) {
    __shared__ float p[4][DF];
    int g0 = blockIdx.x * 4;
    int j = threadIdx.x;                 // 256 threads
    #pragma unroll
    for (int i = j; i < 4 * DF; i += NHID) p[i >> 7][i & 127] = g_pool[g0 * DF + i];
    __syncthreads();
    float bias = bm1[j];
    float a0 = bias, a1 = bias, a2 = bias, a3 = bias;
    #pragma unroll 4
    for (int k = 0; k < DF; k++) {
        float w = Wm1[k * NHID + j];
        a0 += p[0][k] * w; a1 += p[1][k] * w;
        a2 += p[2][k] * w; a3 += p[3][k] * w;
    }
    g_mlp[(g0 + 0) * NHID + j] = fmaxf(a0, 0.f);
    g_mlp[(g0 + 1) * NHID + j] = fmaxf(a1, 0.f);
    g_mlp[(g0 + 2) * NHID + j] = fmaxf(a2, 0.f);
    g_mlp[(g0 + 3) * NHID + j] = fmaxf(a3, 0.f);
}

__global__ void k_mlp2(const float* __restrict__ Wm2, const float* __restrict__ bm2,
                       float* __restrict__ out) {
    __shared__ float p[4][NHID];
    int g0 = blockIdx.x * 4;
    int j = threadIdx.x;                 // 768 threads
    for (int i = j; i < 4 * NHID; i += NOUT) p[i >> 8][i & 255] = g_mlp[g0 * NHID + i];
    __syncthreads();
    float bias = bm2[j];
    float a0 = bias, a1 = bias, a2 = bias, a3 = bias;
    #pragma unroll 4
    for (int k = 0; k < NHID; k++) {
        float w = Wm2[k * NOUT + j];
        a0 += p[0][k] * w; a1 += p[1][k] * w;
        a2 += p[2][k] * w; a3 += p[3][k] * w;
    }
    out[(g0 + 0) * NOUT + j] = a0;
    out[(g0 + 1) * NOUT + j] = a1;
    out[(g0 + 2) * NOUT + j] = a2;
    out[(g0 + 3) * NOUT + j] = a3;
}

// ---------------- launch ----------------
extern "C" void kernel_launch(void* const* d_in, const int* in_sizes, int n_in,
                              void* d_out, int out_size) {
    const float* x     = (const float*)d_in[0];
    const void*  ei    = d_in[1];        // int32 or int64, detected on device
    const void*  batch = d_in[2];
    const float* W1  = (const float*)d_in[3];
    const float* b1  = (const float*)d_in[4];
    const float* W2  = (const float*)d_in[5];
    const float* b2  = (const float*)d_in[6];
    const float* W3  = (const float*)d_in[7];
    const float* b3  = (const float*)d_in[8];
    const float* Wm1 = (const float*)d_in[9];
    const float* bm1 = (const float*)d_in[10];
    const float* Wm2 = (const float*)d_in[11];
    const float* bm2 = (const float*)d_in[12];
    float* out = (float*)d_out;

    const int ZB = (N_NODES + 255) / 256;
    const int EB = (N_EDGES + 255) / 256;
    const int GB = (N_NODES + 127) / 128;        // gemm row tiles
    const int WB = (N_NODES * 32 + 255) / 256;   // warp-per-node kernels

    // dtype detect + CSR build + norms
    k_detect<<<1, 512>>>(ei);
    k_zero  <<<ZB, 256>>>();
    k_deg   <<<EB, 256>>>(ei);
    k_scan1 <<<SCAN_B, 1024>>>();
    k_scan23<<<ZB, 256>>>();             // partial prefix + rowptr + cur + dinv
    k_fill  <<<EB, 256>>>(ei);

    // layer 1
    k_gemm_h<<<GB, 256>>>(x, 0, W1);
    k_gather<<<WB, 256>>>(b1, 1);
    // layer 2
    k_gemm_h<<<GB, 256>>>(nullptr, 1, W2);
    k_gather<<<WB, 256>>>(b2, 1);
    // layer 3 (no relu)
    k_gemm_h<<<GB, 256>>>(nullptr, 1, W3);
    k_gather<<<WB, 256>>>(b3, 0);

    // pooling + MLP head
    k_poolg<<<N_GRAPHS, DF>>>(batch);
    k_mlp1 <<<N_GRAPHS / 4, NHID>>>(Wm1, bm1);
    k_mlp2 <<<N_GRAPHS / 4, NOUT>>>(Wm2, bm2, out);
}

// round 12
// speedup vs baseline: 1.2644x; 1.1804x over previous
#include <cuda_runtime.h>
#include <cuda_fp16.h>

#define N_NODES  50000
#define N_EDGES  800000
#define N_GRAPHS 256
#define DF       128
#define NHID     256
#define NOUT     768
#define SCAN_B   ((N_NODES + 1023) / 1024)

// ---------------- scratch (device globals: no allocs allowed) ----------------
__device__ uint4  g_h16[N_NODES * DF / 8]; // layer features, fp16
__device__ uint2  g_y16[N_NODES * DF / 4]; // dinv-scaled GEMM out, fp16
__device__ __half g_w16[3 * DF * DF];      // W1..W3, fp16, transposed [n][k]
__device__ int    g_deg[N_NODES];
__device__ int    g_rowptr[N_NODES + 1];
__device__ int    g_cur[N_NODES];
__device__ int    g_eidx[N_EDGES];         // CSR-by-dst: src node ids
__device__ float  g_dinv[N_NODES];
__device__ int    g_part[64];
__device__ int    g_is64;                  // 1 if indices are int64, 0 if int32

__device__ __forceinline__ int idx_at(const void* p, long long i, int is64) {
    if (is64) return (int)((const long long*)p)[i];
    return ((const int*)p)[i];
}

// ---------------- zero + dtype detect (fused) ----------------
__global__ void k_zero_detect(const void* ei) {
    int i = blockIdx.x * 256 + threadIdx.x;
    if (i < N_NODES) g_deg[i] = 0;
    if (blockIdx.x == 0) {
        if (threadIdx.x == 0) g_is64 = 1;
        __syncthreads();
        long long v0 = ((const long long*)ei)[threadIdx.x * 2];
        long long v1 = ((const long long*)ei)[threadIdx.x * 2 + 1];
        if (v0 < 0 || v0 >= N_NODES || v1 < 0 || v1 >= N_NODES)
            atomicAnd(&g_is64, 0);
    }
}

// ---------------- W pre-convert: fp32 [k][n] -> fp16 transposed [n][k] -------
__global__ void k_wconv(const float* __restrict__ W1,
                        const float* __restrict__ W2,
                        const float* __restrict__ W3) {
    int e = blockIdx.x * 256 + threadIdx.x;        // 3*16384 total
    int m = e >> 14, r = e & 16383;
    int k = r >> 7, n = r & 127;
    const float* W = (m == 0) ? W1 : ((m == 1) ? W2 : W3);
    g_w16[m * 16384 + n * 128 + k] = __float2half(W[k * 128 + n]);
}

// ---------------- graph preprocessing ----------------
__global__ void k_deg(const void* __restrict__ ei) {
    int e = blockIdx.x * blockDim.x + threadIdx.x;
    if (e < N_EDGES) {
        int d = idx_at(ei, (long long)N_EDGES + e, g_is64);   // dst row
        atomicAdd(&g_deg[d], 1);
    }
}

// warp-shuffle inclusive scan over 1024/block
__global__ void k_scan1() {
    __shared__ int ws[32];
    int tid = threadIdx.x, lane = tid & 31, wid = tid >> 5;
    int i = blockIdx.x * 1024 + tid;
    int val = (i < N_NODES) ? g_deg[i] : 0;
    #pragma unroll
    for (int off = 1; off < 32; off <<= 1) {
        int n = __shfl_up_sync(0xffffffffu, val, off);
        if (lane >= off) val += n;
    }
    if (lane == 31) ws[wid] = val;
    __syncthreads();
    if (wid == 0) {
        int s = ws[lane];
        #pragma unroll
        for (int off = 1; off < 32; off <<= 1) {
            int n = __shfl_up_sync(0xffffffffu, s, off);
            if (lane >= off) s += n;
        }
        ws[lane] = s;
    }
    __syncthreads();
    int inc = val + ((wid > 0) ? ws[wid - 1] : 0);
    if (i < N_NODES) g_rowptr[i + 1] = inc;
    if (tid == 1023) g_part[blockIdx.x] = inc;
}

// fused: partial-prefix + rowptr finalize + cur + dinv
__global__ void k_scan23() {
    __shared__ int base;
    int i = blockIdx.x * 256 + threadIdx.x;
    if (threadIdx.x == 0) {
        int c = (blockIdx.x * 256) >> 10;
        int a = 0;
        for (int b = 0; b < c; b++) a += g_part[b];
        base = a;
    }
    __syncthreads();
    if (i == 0) g_rowptr[0] = 0;
    if (i < N_NODES) {
        int d  = g_deg[i];
        int rp = g_rowptr[i + 1] + base;
        g_rowptr[i + 1] = rp;
        g_cur[i]  = rp - d;
        g_dinv[i] = rsqrtf((float)(d + 1));   // +1 self loop; always > 0
    }
}

__global__ void k_fill(const void* __restrict__ ei) {
    int e = blockIdx.x * blockDim.x + threadIdx.x;
    if (e < N_EDGES) {
        int is64 = g_is64;
        int s = idx_at(ei, e, is64);                         // src
        int d = idx_at(ei, (long long)N_EDGES + e, is64);    // dst
        int pos = atomicAdd(&g_cur[d], 1);
        g_eidx[pos] = s;
    }
}

// ---------------- tensor-core GEMM (fp16 m16n8k16 mma.sync, fp32 accum) ------
// y16[v,:] = fp16( (X @ W)[v,:] * dinv[v] ).  B pre-converted fp16 in g_w16.
#define PA 72   // halves pitch
#define PB 72

__device__ __forceinline__ void mma_f16(float* d,
                                        const unsigned* a, const unsigned* b,
                                        const float* c) {
    asm volatile(
        "mma.sync.aligned.m16n8k16.row.col.f32.f16.f16.f32 "
        "{%0,%1,%2,%3}, {%4,%5,%6,%7}, {%8,%9}, {%10,%11,%12,%13};\n"
        : "=f"(d[0]), "=f"(d[1]), "=f"(d[2]), "=f"(d[3])
        : "r"(a[0]), "r"(a[1]), "r"(a[2]), "r"(a[3]),
          "r"(b[0]), "r"(b[1]),
          "f"(c[0]), "f"(c[1]), "f"(c[2]), "f"(c[3]));
}

__global__ void __launch_bounds__(256) k_gemm_h(const float* __restrict__ Xf,
                                                int use_h16, int widx) {
    __shared__ __half As[128 * PA];
    __shared__ __half Bs[128 * PB];
    int tid  = threadIdx.x;
    int wid  = tid >> 5, lane = tid & 31;
    int wm   = wid >> 1, wn = wid & 1;       // 4 x 2 warps
    int grp  = lane >> 2, tig = lane & 3;
    int row0 = blockIdx.x * 128;
    const uint4* wt4 = (const uint4*)&g_w16[widx * 16384];

    float acc[2][8][4] = {};

    for (int kt = 0; kt < 128; kt += 64) {
        // ---- A tile: 128 rows x 64 halves ----
        if (use_h16) {
            #pragma unroll
            for (int i = 0; i < 4; i++) {
                int idx = tid + i * 256;          // 1024 uint4
                int r = idx >> 3, q = idx & 7;
                int grow = row0 + r;
                uint4 u = (grow < N_NODES) ? g_h16[grow * 16 + (kt >> 3) + q]
                                           : make_uint4(0, 0, 0, 0);
                *(uint4*)&As[r * PA + q * 8] = u;
            }
        } else {
            #pragma unroll
            for (int i = 0; i < 4; i++) {
                int idx = tid + i * 256;
                int r = idx >> 3, q = idx & 7;
                int grow = row0 + r;
                uint4 u = make_uint4(0, 0, 0, 0);
                if (grow < N_NODES) {
                    const float4* xp = (const float4*)&Xf[grow * 128 + kt + q * 8];
                    float4 f0 = xp[0], f1 = xp[1];
                    *(__half2*)&u.x = __floats2half2_rn(f0.x, f0.y);
                    *(__half2*)&u.y = __floats2half2_rn(f0.z, f0.w);
                    *(__half2*)&u.z = __floats2half2_rn(f1.x, f1.y);
                    *(__half2*)&u.w = __floats2half2_rn(f1.z, f1.w);
                }
                *(uint4*)&As[r * PA + q * 8] = u;
            }
        }
        // ---- B tile: straight fp16 copy from pre-transposed g_w16 ----
        #pragma unroll
        for (int i = 0; i < 4; i++) {
            int idx = tid + i * 256;              // 1024 uint4
            int n = idx >> 3, q = idx & 7;
            uint4 u = wt4[n * 16 + (kt >> 3) + q];
            *(uint4*)&Bs[n * PB + q * 8] = u;
        }
        __syncthreads();

        #pragma unroll
        for (int ka = 0; ka < 4; ka++) {
            int kb = ka * 16;
            unsigned a[2][4], bf[8][2];
            #pragma unroll
            for (int m = 0; m < 2; m++) {
                int r = wm * 32 + m * 16 + grp;
                a[m][0] = *(unsigned*)&As[r * PA + kb + 2 * tig];
                a[m][1] = *(unsigned*)&As[(r + 8) * PA + kb + 2 * tig];
                a[m][2] = *(unsigned*)&As[r * PA + kb + 8 + 2 * tig];
                a[m][3] = *(unsigned*)&As[(r + 8) * PA + kb + 8 + 2 * tig];
            }
            #pragma unroll
            for (int n = 0; n < 8; n++) {
                int cn = wn * 64 + n * 8 + grp;
                bf[n][0] = *(unsigned*)&Bs[cn * PB + kb + 2 * tig];
                bf[n][1] = *(unsigned*)&Bs[cn * PB + kb + 8 + 2 * tig];
            }
            #pragma unroll
            for (int m = 0; m < 2; m++)
                #pragma unroll
                for (int n = 0; n < 8; n++)
                    mma_f16(acc[m][n], a[m], bf[n], acc[m][n]);
        }
        __syncthreads();
    }

    // epilogue: scale by dinv, fp16 half2 stores
    __half2* yp = (__half2*)g_y16;
    #pragma unroll
    for (int m = 0; m < 2; m++) {
        #pragma unroll
        for (int hf = 0; hf < 2; hf++) {
            int row = row0 + wm * 32 + m * 16 + grp + hf * 8;
            if (row < N_NODES) {
                float dv = g_dinv[row];
                #pragma unroll
                for (int n = 0; n < 8; n++) {
                    int col = wn * 64 + n * 8 + 2 * tig;
                    yp[row * 64 + (col >> 1)] =
                        __floats2half2_rn(acc[m][n][hf * 2] * dv,
                                          acc[m][n][hf * 2 + 1] * dv);
                }
            }
        }
    }
}

// ---------------- gather-sum: warp/node, 32 lanes x uint2, 4-deep unroll -----
__device__ __forceinline__ void acc_row(float4& a, uint2 raw) {
    float2 lo = __half22float2(*(__half2*)&raw.x);
    float2 hi = __half22float2(*(__half2*)&raw.y);
    a.x += lo.x; a.y += lo.y; a.z += hi.x; a.w += hi.y;
}

__global__ void k_gather(const float* __restrict__ b, int relu) {
    int t = blockIdx.x * blockDim.x + threadIdx.x;
    int v = t >> 5;
    int lane = t & 31;
    if (v >= N_NODES) return;
    const uint2* yp = (const uint2*)g_y16;
    float4 acc = make_float4(0.f, 0.f, 0.f, 0.f);
    acc_row(acc, __ldg(&yp[v * 32 + lane]));        // self loop
    int e = g_rowptr[v], end = g_rowptr[v + 1];
    for (; e + 3 < end; e += 4) {                   // 4 rows in flight
        int s0 = g_eidx[e],     s1 = g_eidx[e + 1];
        int s2 = g_eidx[e + 2], s3 = g_eidx[e + 3];
        uint2 r0 = __ldg(&yp[s0 * 32 + lane]);
        uint2 r1 = __ldg(&yp[s1 * 32 + lane]);
        uint2 r2 = __ldg(&yp[s2 * 32 + lane]);
        uint2 r3 = __ldg(&yp[s3 * 32 + lane]);
        acc_row(acc, r0); acc_row(acc, r1);
        acc_row(acc, r2); acc_row(acc, r3);
    }
    for (; e < end; e++) acc_row(acc, __ldg(&yp[g_eidx[e] * 32 + lane]));

    float dv = g_dinv[v];
    float4 bb = ((const float4*)b)[lane];
    float o0 = dv * acc.x + bb.x, o1 = dv * acc.y + bb.y;
    float o2 = dv * acc.z + bb.z, o3 = dv * acc.w + bb.w;
    if (relu) {
        o0 = fmaxf(o0, 0.f); o1 = fmaxf(o1, 0.f);
        o2 = fmaxf(o2, 0.f); o3 = fmaxf(o3, 0.f);
    }
    uint2 w;
    *(__half2*)&w.x = __floats2half2_rn(o0, o1);
    *(__half2*)&w.y = __floats2half2_rn(o2, o3);
    ((uint2*)g_h16)[v * 32 + lane] = w;
}

// ---------------- fused tail: mean-pool + MLP1 + MLP2 (4 graphs / block) -----
__global__ void __launch_bounds__(768) k_tail(const void* __restrict__ batch,
                                              const float* __restrict__ Wm1,
                                              const float* __restrict__ bm1,
                                              const float* __restrict__ Wm2,
                                              const float* __restrict__ bm2,
                                              float* __restrict__ out) {
    __shared__ float p[4][DF];
    __shared__ float q[4][NHID];
    int g0 = blockIdx.x * 4;
    int tid = threadIdx.x;
    int is64 = g_is64;

    // phase 1: mean pool (512 threads: 4 graphs x 128 dims)
    if (tid < 512) {
        int gl = tid >> 7, dim = tid & 127;
        int g = g0 + gl;
        int lo = 0, hi = N_NODES;
        while (lo < hi) { int m = (lo + hi) >> 1; if (idx_at(batch, m, is64) < g) lo = m + 1; else hi = m; }
        int beg = lo;
        lo = 0; hi = N_NODES;
        while (lo < hi) { int m = (lo + hi) >> 1; if (idx_at(batch, m, is64) <= g) lo = m + 1; else hi = m; }
        int end = lo;
        const __half* hp = (const __half*)g_h16;
        float acc = 0.f;
        for (int v = beg; v < end; v++) acc += __half2float(hp[v * DF + dim]);
        p[gl][dim] = (end > beg) ? acc / (float)(end - beg) : 0.f;
    }
    __syncthreads();

    // phase 2: MLP1 (256 threads, 4 graphs each)
    if (tid < NHID) {
        int j = tid;
        float bias = bm1[j];
        float a0 = bias, a1 = bias, a2 = bias, a3 = bias;
        #pragma unroll 4
        for (int k = 0; k < DF; k++) {
            float w = Wm1[k * NHID + j];
            a0 += p[0][k] * w; a1 += p[1][k] * w;
            a2 += p[2][k] * w; a3 += p[3][k] * w;
        }
        q[0][j] = fmaxf(a0, 0.f); q[1][j] = fmaxf(a1, 0.f);
        q[2][j] = fmaxf(a2, 0.f); q[3][j] = fmaxf(a3, 0.f);
    }
    __syncthreads();

    // phase 3: MLP2 (768 threads, 4 graphs each)
    {
        int j = tid;
        float bias = bm2[j];
        float a0 = bias, a1 = bias, a2 = bias, a3 = bias;
        #pragma unroll 4
        for (int k = 0; k < NHID; k++) {
            float w = Wm2[k * NOUT + j];
            a0 += q[0][k] * w; a1 += q[1][k] * w;
            a2 += q[2][k] * w; a3 += q[3][k] * w;
        }
        out[(g0 + 0) * NOUT + j] = a0;
        out[(g0 + 1) * NOUT + j] = a1;
        out[(g0 + 2) * NOUT + j] = a2;
        out[(g0 + 3) * NOUT + j] = a3;
    }
}

// ---------------- launch ----------------
extern "C" void kernel_launch(void* const* d_in, const int* in_sizes, int n_in,
                              void* d_out, int out_size) {
    const float* x     = (const float*)d_in[0];
    const void*  ei    = d_in[1];        // int32 or int64, detected on device
    const void*  batch = d_in[2];
    const float* W1  = (const float*)d_in[3];
    const float* b1  = (const float*)d_in[4];
    const float* W2  = (const float*)d_in[5];
    const float* b2  = (const float*)d_in[6];
    const float* W3  = (const float*)d_in[7];
    const float* b3  = (const float*)d_in[8];
    const float* Wm1 = (const float*)d_in[9];
    const float* bm1 = (const float*)d_in[10];
    const float* Wm2 = (const float*)d_in[11];
    const float* bm2 = (const float*)d_in[12];
    float* out = (float*)d_out;

    const int ZB = (N_NODES + 255) / 256;
    const int EB = (N_EDGES + 255) / 256;
    const int GB = (N_NODES + 127) / 128;        // gemm row tiles
    const int WB = (N_NODES * 32 + 255) / 256;   // warp-per-node kernels

    // preprocessing
    k_zero_detect<<<ZB, 256>>>(ei);
    k_wconv <<<192, 256>>>(W1, W2, W3);
    k_deg   <<<EB, 256>>>(ei);
    k_scan1 <<<SCAN_B, 1024>>>();
    k_scan23<<<ZB, 256>>>();             // partial prefix + rowptr + cur + dinv
    k_fill  <<<EB, 256>>>(ei);

    // layer 1
    k_gemm_h<<<GB, 256>>>(x, 0, 0);
    k_gather<<<WB, 256>>>(b1, 1);
    // layer 2
    k_gemm_h<<<GB, 256>>>(nullptr, 1, 1);
    k_gather<<<WB, 256>>>(b2, 1);
    // layer 3 (no relu)
    k_gemm_h<<<GB, 256>>>(nullptr, 1, 2);
    k_gather<<<WB, 256>>>(b3, 0);

    // fused pooling + MLP head
    k_tail<<<N_GRAPHS / 4, 768>>>(batch, Wm1, bm1, Wm2, bm2, out);
}